// round 1
// baseline (speedup 1.0000x reference)
#include <cuda_runtime.h>
#include <math.h>

#define B_  2
#define S_  2048
#define H_  16
#define HD_ 128
#define D_  2048
#define M_  (B_ * S_)   // 4096

// ---------------- scratch (static device globals; no allocation) ----------------
__device__ float g_q[(size_t)M_ * D_];
__device__ float g_k[(size_t)M_ * D_];
__device__ float g_v[(size_t)M_ * D_];
__device__ float g_ao[(size_t)M_ * D_];

// ---------------- SGEMM: C[m,n] = scale * (sum_k A[m,k]*W[n,k] + bias[n]) -------
// A: [M,K] row-major, W: [N,K] row-major (i.e. x @ W^T), both K-contiguous.
// Tile 128x128x8, 256 threads, 8x8 micro-tile with 16-strided row/col mapping.
__global__ __launch_bounds__(256) void sgemm_tn_bias(
    const float* __restrict__ A, const float* __restrict__ W,
    const float* __restrict__ bias, float* __restrict__ C,
    int M, int N, int K, float scale)
{
    __shared__ float As[8][128];
    __shared__ float Bs[8][128];

    const int tid = threadIdx.x;
    const int tx = tid & 15;      // 0..15
    const int ty = tid >> 4;      // 0..15
    const int bm = blockIdx.y * 128;
    const int bn = blockIdx.x * 128;

    const int lrow = tid >> 1;          // 0..127
    const int lk4  = (tid & 1) * 4;     // 0 or 4

    const float* Aptr = A + (size_t)(bm + lrow) * K + lk4;
    const float* Wptr = W + (size_t)(bn + lrow) * K + lk4;

    float acc[8][8];
    #pragma unroll
    for (int i = 0; i < 8; i++)
        #pragma unroll
        for (int j = 0; j < 8; j++) acc[i][j] = 0.f;

    for (int k0 = 0; k0 < K; k0 += 8) {
        float4 a4 = *(const float4*)(Aptr + k0);
        float4 w4 = *(const float4*)(Wptr + k0);
        __syncthreads();   // previous tile fully consumed
        As[lk4 + 0][lrow] = a4.x;
        As[lk4 + 1][lrow] = a4.y;
        As[lk4 + 2][lrow] = a4.z;
        As[lk4 + 3][lrow] = a4.w;
        Bs[lk4 + 0][lrow] = w4.x;
        Bs[lk4 + 1][lrow] = w4.y;
        Bs[lk4 + 2][lrow] = w4.z;
        Bs[lk4 + 3][lrow] = w4.w;
        __syncthreads();

        #pragma unroll
        for (int k = 0; k < 8; k++) {
            float ra[8], rb[8];
            #pragma unroll
            for (int i = 0; i < 8; i++) ra[i] = As[k][ty + 16 * i];
            #pragma unroll
            for (int j = 0; j < 8; j++) rb[j] = Bs[k][tx + 16 * j];
            #pragma unroll
            for (int i = 0; i < 8; i++)
                #pragma unroll
                for (int j = 0; j < 8; j++)
                    acc[i][j] = fmaf(ra[i], rb[j], acc[i][j]);
        }
    }

    #pragma unroll
    for (int i = 0; i < 8; i++) {
        const int row = bm + ty + 16 * i;
        #pragma unroll
        for (int j = 0; j < 8; j++) {
            const int col = bn + tx + 16 * j;
            C[(size_t)row * N + col] = scale * (acc[i][j] + bias[col]);
        }
    }
}

// ---------------- Flash attention (fp32, causal) --------------------------------
// grid: (S/64, B*H). 256 threads. BQ=BK=64.
// q,k,v,o in [B,S,H*HD] layout; head slice contiguous (HD floats).
#define BQ 64
#define BKT 64
// smem floats: 3*64*129 + 64*65 + 3*64
#define ATTN_SMEM_FLOATS (3 * 64 * 129 + 64 * 65 + 3 * 64)

__global__ __launch_bounds__(256) void attn_kernel(
    const float* __restrict__ q, const float* __restrict__ k,
    const float* __restrict__ v, float* __restrict__ o)
{
    extern __shared__ float sm[];
    float* Qs   = sm;                    // [64][129]
    float* Ks   = Qs + 64 * 129;         // [64][129]
    float* Vs   = Ks + 64 * 129;         // [64][129]
    float* Ps   = Vs + 64 * 129;         // [64][65]
    float* sm_m = Ps + 64 * 65;          // [64]
    float* sm_l = sm_m + 64;             // [64]
    float* sm_a = sm_l + 64;             // [64]

    const int tid = threadIdx.x;
    const int tx = tid & 15;
    const int ty = tid >> 4;
    const int qt = blockIdx.x;
    const int bh = blockIdx.y;
    const int b  = bh >> 4;              // H=16
    const int h  = bh & 15;
    const int q0 = qt * BQ;
    const size_t headoff = (size_t)h * HD_;

    // load Q tile: 64 rows x 128 = 2048 float4
    for (int i = tid; i < 2048; i += 256) {
        const int r  = i >> 5;
        const int c4 = (i & 31) << 2;
        float4 qv = *(const float4*)(q + (size_t)(b * S_ + q0 + r) * D_ + headoff + c4);
        float* dst = Qs + r * 129 + c4;
        dst[0] = qv.x; dst[1] = qv.y; dst[2] = qv.z; dst[3] = qv.w;
    }
    if (tid < 64) { sm_m[tid] = -INFINITY; sm_l[tid] = 0.f; }

    float acc[4][8];
    #pragma unroll
    for (int i = 0; i < 4; i++)
        #pragma unroll
        for (int j = 0; j < 8; j++) acc[i][j] = 0.f;

    __syncthreads();

    for (int kt = 0; kt <= qt; kt++) {
        const int k0 = kt * BKT;
        // load K, V tiles
        for (int i = tid; i < 2048; i += 256) {
            const int r  = i >> 5;
            const int c4 = (i & 31) << 2;
            const size_t base = (size_t)(b * S_ + k0 + r) * D_ + headoff + c4;
            float4 kv = *(const float4*)(k + base);
            float4 vv = *(const float4*)(v + base);
            float* kd = Ks + r * 129 + c4;
            float* vd = Vs + r * 129 + c4;
            kd[0] = kv.x; kd[1] = kv.y; kd[2] = kv.z; kd[3] = kv.w;
            vd[0] = vv.x; vd[1] = vv.y; vd[2] = vv.z; vd[3] = vv.w;
        }
        __syncthreads();

        // scores: 4x4 per thread, rows ty+16i, cols tx+16j
        float s[4][4];
        #pragma unroll
        for (int i = 0; i < 4; i++)
            #pragma unroll
            for (int j = 0; j < 4; j++) s[i][j] = 0.f;

        #pragma unroll 4
        for (int kk = 0; kk < HD_; kk++) {
            float qa[4], kb[4];
            #pragma unroll
            for (int i = 0; i < 4; i++) qa[i] = Qs[(ty + 16 * i) * 129 + kk];
            #pragma unroll
            for (int j = 0; j < 4; j++) kb[j] = Ks[(tx + 16 * j) * 129 + kk];
            #pragma unroll
            for (int i = 0; i < 4; i++)
                #pragma unroll
                for (int j = 0; j < 4; j++)
                    s[i][j] = fmaf(qa[i], kb[j], s[i][j]);
        }

        const bool diag = (kt == qt);
        #pragma unroll
        for (int i = 0; i < 4; i++) {
            const int qr = q0 + ty + 16 * i;
            #pragma unroll
            for (int j = 0; j < 4; j++) {
                const int kc = k0 + tx + 16 * j;
                float val = s[i][j];
                if (diag && kc > qr) val = -1e30f;
                Ps[(ty + 16 * i) * 65 + tx + 16 * j] = val;
            }
        }
        __syncthreads();

        // online softmax: one thread per row
        if (tid < 64) {
            float* prow = Ps + tid * 65;
            float mOld = sm_m[tid];
            float mx = mOld;
            #pragma unroll 8
            for (int c = 0; c < 64; c++) mx = fmaxf(mx, prow[c]);
            const float alpha = __expf(mOld - mx);
            float sum = 0.f;
            #pragma unroll 8
            for (int c = 0; c < 64; c++) {
                const float p = __expf(prow[c] - mx);
                prow[c] = p;
                sum += p;
            }
            sm_l[tid] = sm_l[tid] * alpha + sum;
            sm_m[tid] = mx;
            sm_a[tid] = alpha;
        }
        __syncthreads();

        // rescale + PV
        float al[4];
        #pragma unroll
        for (int i = 0; i < 4; i++) al[i] = sm_a[ty + 16 * i];
        #pragma unroll
        for (int i = 0; i < 4; i++)
            #pragma unroll
            for (int j = 0; j < 8; j++) acc[i][j] *= al[i];

        #pragma unroll 2
        for (int kk = 0; kk < BKT; kk++) {
            float p[4], vv[8];
            #pragma unroll
            for (int i = 0; i < 4; i++) p[i] = Ps[(ty + 16 * i) * 65 + kk];
            #pragma unroll
            for (int j = 0; j < 8; j++) vv[j] = Vs[kk * 129 + tx + 16 * j];
            #pragma unroll
            for (int i = 0; i < 4; i++)
                #pragma unroll
                for (int j = 0; j < 8; j++)
                    acc[i][j] = fmaf(p[i], vv[j], acc[i][j]);
        }
        __syncthreads();   // tiles consumed before next load
    }

    #pragma unroll
    for (int i = 0; i < 4; i++) {
        const int r = ty + 16 * i;
        const float inv = 1.f / sm_l[r];
        const size_t base = (size_t)(b * S_ + q0 + r) * D_ + headoff;
        #pragma unroll
        for (int j = 0; j < 8; j++)
            o[base + tx + 16 * j] = acc[i][j] * inv;
    }
}

// ---------------- launch ---------------------------------------------------------
extern "C" void kernel_launch(void* const* d_in, const int* in_sizes, int n_in,
                              void* d_out, int out_size)
{
    const float* x  = (const float*)d_in[0];
    const float* Wq = (const float*)d_in[1];
    const float* bq = (const float*)d_in[2];
    const float* Wk = (const float*)d_in[3];
    const float* bk = (const float*)d_in[4];
    const float* Wv = (const float*)d_in[5];
    const float* bv = (const float*)d_in[6];
    const float* Wo = (const float*)d_in[7];
    const float* bo = (const float*)d_in[8];
    float* out = (float*)d_out;

    float *q, *k, *v, *ao;
    cudaGetSymbolAddress((void**)&q,  g_q);
    cudaGetSymbolAddress((void**)&k,  g_k);
    cudaGetSymbolAddress((void**)&v,  g_v);
    cudaGetSymbolAddress((void**)&ao, g_ao);

    const size_t attn_smem = ATTN_SMEM_FLOATS * sizeof(float);
    static bool attr_done = false;
    if (!attr_done) {
        cudaFuncSetAttribute(attn_kernel, cudaFuncAttributeMaxDynamicSharedMemorySize,
                             (int)attn_smem);
        attr_done = true;
    }

    dim3 gGrid(D_ / 128, M_ / 128);   // (16, 32)
    const float qscale = 1.0f / sqrtf((float)HD_);

    sgemm_tn_bias<<<gGrid, 256>>>(x, Wq, bq, q, M_, D_, D_, qscale);
    sgemm_tn_bias<<<gGrid, 256>>>(x, Wk, bk, k, M_, D_, D_, 1.0f);
    sgemm_tn_bias<<<gGrid, 256>>>(x, Wv, bv, v, M_, D_, D_, 1.0f);

    dim3 aGrid(S_ / BQ, B_ * H_);     // (32, 32)
    attn_kernel<<<aGrid, 256, attn_smem>>>(q, k, v, ao);

    sgemm_tn_bias<<<gGrid, 256>>>(ao, Wo, bo, out, M_, D_, D_, 1.0f);
}

// round 4
// speedup vs baseline: 1.7794x; 1.7794x over previous
#include <cuda_runtime.h>
#include <cuda_bf16.h>
#include <math.h>
#include <stdint.h>

#define B_  2
#define S_  2048
#define H_  16
#define HD_ 128
#define D_  2048
#define M_  (B_ * S_)   // 4096

// ---------------- scratch (static device globals; no allocation) ----------------
__device__ float g_q[(size_t)M_ * D_];
__device__ float g_k[(size_t)M_ * D_];
__device__ float g_v[(size_t)M_ * D_];
__device__ float g_ao[(size_t)M_ * D_];
__device__ unsigned short g_xhi[(size_t)M_ * D_];
__device__ unsigned short g_xlo[(size_t)M_ * D_];
__device__ unsigned short g_aohi[(size_t)M_ * D_];
__device__ unsigned short g_aolo[(size_t)M_ * D_];
__device__ unsigned short g_whi[4][(size_t)D_ * D_];
__device__ unsigned short g_wlo[4][(size_t)D_ * D_];

__device__ __forceinline__ uint32_t smem_to_u32(const void* p) {
    uint32_t a;
    asm("{ .reg .u64 t; cvta.to.shared.u64 t, %1; cvt.u32.u64 %0, t; }" : "=r"(a) : "l"(p));
    return a;
}

#define LDMATRIX_X4(r0, r1, r2, r3, addr) \
    asm volatile("ldmatrix.sync.aligned.m8n8.x4.shared.b16 {%0,%1,%2,%3}, [%4];" \
                 : "=r"(r0), "=r"(r1), "=r"(r2), "=r"(r3) : "r"(addr))

#define MMA_BF16(d, a, b) \
    asm volatile("mma.sync.aligned.m16n8k16.row.col.f32.bf16.bf16.f32 " \
                 "{%0,%1,%2,%3}, {%4,%5,%6,%7}, {%8,%9}, {%0,%1,%2,%3};" \
                 : "+f"((d)[0]), "+f"((d)[1]), "+f"((d)[2]), "+f"((d)[3]) \
                 : "r"((a)[0]), "r"((a)[1]), "r"((a)[2]), "r"((a)[3]), \
                   "r"((b)[0]), "r"((b)[1]))

#define CP_ASYNC_16(dst, src) \
    asm volatile("cp.async.cg.shared.global [%0], [%1], 16;" :: "r"(dst), "l"(src))
#define CP_ASYNC_COMMIT() asm volatile("cp.async.commit_group;" ::: "memory")
#define CP_ASYNC_WAIT1()  asm volatile("cp.async.wait_group 1;" ::: "memory")

// ---------------- split fp32 -> bf16 hi/lo ---------------------------------------
__global__ __launch_bounds__(256) void split_kernel(
    const float4* __restrict__ in, ushort4* __restrict__ hi, ushort4* __restrict__ lo, int n4)
{
    int i = blockIdx.x * blockDim.x + threadIdx.x;
    if (i >= n4) return;
    float4 x = in[i];
    __nv_bfloat16 h0 = __float2bfloat16(x.x);
    __nv_bfloat16 h1 = __float2bfloat16(x.y);
    __nv_bfloat16 h2 = __float2bfloat16(x.z);
    __nv_bfloat16 h3 = __float2bfloat16(x.w);
    ushort4 hv, lv;
    hv.x = __bfloat16_as_ushort(h0);
    hv.y = __bfloat16_as_ushort(h1);
    hv.z = __bfloat16_as_ushort(h2);
    hv.w = __bfloat16_as_ushort(h3);
    lv.x = __bfloat16_as_ushort(__float2bfloat16(x.x - __bfloat162float(h0)));
    lv.y = __bfloat16_as_ushort(__float2bfloat16(x.y - __bfloat162float(h1)));
    lv.z = __bfloat16_as_ushort(__float2bfloat16(x.z - __bfloat162float(h2)));
    lv.w = __bfloat16_as_ushort(__float2bfloat16(x.w - __bfloat162float(h3)));
    hi[i] = hv;
    lo[i] = lv;
}

// ---------------- HMMA bf16x3 GEMM: C = scale*(A @ W^T + bias) -------------------
// A[M,K], W[N,K] row-major (K-contiguous). Block 128x128, K-chunk 32, 8 warps,
// warp tile 64x32 via m16n8k16. Smem rows padded to 80B (conflict-free ldmatrix).
#define BKC 32
#define NCH (D_ / BKC)             // 64
#define ROW_B 80                   // bytes per smem row (32 bf16 + 8 pad)
#define TILE_SB (128 * ROW_B)      // 10240 B per 128x32 tile
#define BUF_SB (4 * TILE_SB)       // Ahi, Alo, Bhi, Blo = 40960 B
#define GEMM_SMEM (2 * BUF_SB)     // 81920 B

__global__ __launch_bounds__(256) void gemm_mma_bf16x3(
    const unsigned short* __restrict__ Ahi, const unsigned short* __restrict__ Alo,
    const unsigned short* __restrict__ Bhi, const unsigned short* __restrict__ Blo,
    const float* __restrict__ bias, float* __restrict__ C, float scale)
{
    extern __shared__ __align__(16) unsigned short smem_us[];
    const uint32_t sb = smem_to_u32(smem_us);

    const int tid  = threadIdx.x;
    const int lane = tid & 31;
    const int wid  = tid >> 5;
    const int wm   = wid >> 2;   // 0..1  -> rows wm*64
    const int wn   = wid & 3;    // 0..3  -> cols wn*32
    const int bm   = blockIdx.y * 128;
    const int bn   = blockIdx.x * 128;

    float acc[4][4][4];
    #pragma unroll
    for (int i = 0; i < 4; i++)
        #pragma unroll
        for (int j = 0; j < 4; j++)
            #pragma unroll
            for (int r = 0; r < 4; r++) acc[i][j][r] = 0.f;

    // ---- async loader: chunk c -> buffer buf ----
    auto load_chunk = [&](int c, int buf) {
        const int k0 = c * BKC;
        const uint32_t sbase = sb + buf * BUF_SB;
        #pragma unroll
        for (int t = 0; t < 8; t++) {
            const int tile = t >> 1;                    // 0:Ahi 1:Alo 2:Bhi 3:Blo
            const int idx  = tid + (t & 1) * 256;       // 0..511
            const int r    = idx >> 2;                  // row 0..127
            const int c16  = idx & 3;                   // 16B segment 0..3
            const unsigned short* g =
                (tile == 0) ? Ahi : (tile == 1) ? Alo : (tile == 2) ? Bhi : Blo;
            const int grow = ((tile < 2) ? bm : bn) + r;
            const unsigned short* src = g + (size_t)grow * D_ + k0 + c16 * 8;
            const uint32_t dst = sbase + tile * TILE_SB + r * ROW_B + c16 * 16;
            CP_ASYNC_16(dst, src);
        }
        CP_ASYNC_COMMIT();
    };

    load_chunk(0, 0);
    load_chunk(1, 1);

    // per-lane ldmatrix address components
    const int a_row  = wm * 64 + (lane & 15);        // + mt*16
    const int a_cadd = (lane >> 4) * 8;              // + ks*16
    const int b_i    = lane >> 3;
    const int b_row  = wn * 32 + (b_i >> 1) * 8 + (lane & 7);   // + np*16
    const int b_cadd = (b_i & 1) * 8;                // + ks*16

    for (int c = 0; c < NCH; c++) {
        CP_ASYNC_WAIT1();
        __syncthreads();

        const uint32_t sbase = sb + (c & 1) * BUF_SB;
        const uint32_t ah_b = sbase;
        const uint32_t al_b = sbase + TILE_SB;
        const uint32_t bh_b = sbase + 2 * TILE_SB;
        const uint32_t bl_b = sbase + 3 * TILE_SB;

        #pragma unroll
        for (int ks = 0; ks < 2; ks++) {
            const int kb = ks * 16;
            uint32_t ah[4][4], al[4][4];
            #pragma unroll
            for (int mt = 0; mt < 4; mt++) {
                const uint32_t off = (uint32_t)(a_row + mt * 16) * ROW_B + (kb + a_cadd) * 2;
                LDMATRIX_X4(ah[mt][0], ah[mt][1], ah[mt][2], ah[mt][3], ah_b + off);
                LDMATRIX_X4(al[mt][0], al[mt][1], al[mt][2], al[mt][3], al_b + off);
            }
            uint32_t bh[4][2], bl[4][2];
            #pragma unroll
            for (int np = 0; np < 2; np++) {
                const uint32_t off = (uint32_t)(b_row + np * 16) * ROW_B + (kb + b_cadd) * 2;
                LDMATRIX_X4(bh[np*2][0], bh[np*2][1], bh[np*2+1][0], bh[np*2+1][1], bh_b + off);
                LDMATRIX_X4(bl[np*2][0], bl[np*2][1], bl[np*2+1][0], bl[np*2+1][1], bl_b + off);
            }
            #pragma unroll
            for (int mt = 0; mt < 4; mt++)
                #pragma unroll
                for (int nt = 0; nt < 4; nt++) {
                    MMA_BF16(acc[mt][nt], ah[mt], bh[nt]);   // hi*hi
                    MMA_BF16(acc[mt][nt], ah[mt], bl[nt]);   // hi*lo
                    MMA_BF16(acc[mt][nt], al[mt], bh[nt]);   // lo*hi
                }
        }

        __syncthreads();
        if (c + 2 < NCH) load_chunk(c + 2, c & 1);
    }

    // ---- epilogue ----
    const int g  = lane >> 2;          // 0..7
    const int tq = lane & 3;           // 0..3
    #pragma unroll
    for (int nt = 0; nt < 4; nt++) {
        const int col = bn + wn * 32 + nt * 8 + tq * 2;
        const float b0 = bias[col], b1 = bias[col + 1];
        #pragma unroll
        for (int mt = 0; mt < 4; mt++) {
            const int r0 = bm + wm * 64 + mt * 16 + g;
            float2 v0 = make_float2(scale * (acc[mt][nt][0] + b0),
                                    scale * (acc[mt][nt][1] + b1));
            float2 v1 = make_float2(scale * (acc[mt][nt][2] + b0),
                                    scale * (acc[mt][nt][3] + b1));
            *(float2*)(C + (size_t)r0 * D_ + col)       = v0;
            *(float2*)(C + (size_t)(r0 + 8) * D_ + col) = v1;
        }
    }
}

// ---------------- Flash attention (fp32, causal) — unchanged from R1 -------------
#define BQ 64
#define BKT 64
#define ATTN_SMEM_FLOATS (3 * 64 * 129 + 64 * 65 + 3 * 64)

__global__ __launch_bounds__(256) void attn_kernel(
    const float* __restrict__ q, const float* __restrict__ k,
    const float* __restrict__ v, float* __restrict__ o)
{
    extern __shared__ float sm[];
    float* Qs   = sm;
    float* Ks   = Qs + 64 * 129;
    float* Vs   = Ks + 64 * 129;
    float* Ps   = Vs + 64 * 129;
    float* sm_m = Ps + 64 * 65;
    float* sm_l = sm_m + 64;
    float* sm_a = sm_l + 64;

    const int tid = threadIdx.x;
    const int tx = tid & 15;
    const int ty = tid >> 4;
    const int qt = blockIdx.x;
    const int bh = blockIdx.y;
    const int b  = bh >> 4;
    const int h  = bh & 15;
    const int q0 = qt * BQ;
    const size_t headoff = (size_t)h * HD_;

    for (int i = tid; i < 2048; i += 256) {
        const int r  = i >> 5;
        const int c4 = (i & 31) << 2;
        float4 qv = *(const float4*)(q + (size_t)(b * S_ + q0 + r) * D_ + headoff + c4);
        float* dst = Qs + r * 129 + c4;
        dst[0] = qv.x; dst[1] = qv.y; dst[2] = qv.z; dst[3] = qv.w;
    }
    if (tid < 64) { sm_m[tid] = -INFINITY; sm_l[tid] = 0.f; }

    float acc[4][8];
    #pragma unroll
    for (int i = 0; i < 4; i++)
        #pragma unroll
        for (int j = 0; j < 8; j++) acc[i][j] = 0.f;

    __syncthreads();

    for (int kt = 0; kt <= qt; kt++) {
        const int k0 = kt * BKT;
        for (int i = tid; i < 2048; i += 256) {
            const int r  = i >> 5;
            const int c4 = (i & 31) << 2;
            const size_t base = (size_t)(b * S_ + k0 + r) * D_ + headoff + c4;
            float4 kv = *(const float4*)(k + base);
            float4 vv = *(const float4*)(v + base);
            float* kd = Ks + r * 129 + c4;
            float* vd = Vs + r * 129 + c4;
            kd[0] = kv.x; kd[1] = kv.y; kd[2] = kv.z; kd[3] = kv.w;
            vd[0] = vv.x; vd[1] = vv.y; vd[2] = vv.z; vd[3] = vv.w;
        }
        __syncthreads();

        float s[4][4];
        #pragma unroll
        for (int i = 0; i < 4; i++)
            #pragma unroll
            for (int j = 0; j < 4; j++) s[i][j] = 0.f;

        #pragma unroll 4
        for (int kk = 0; kk < HD_; kk++) {
            float qa[4], kb[4];
            #pragma unroll
            for (int i = 0; i < 4; i++) qa[i] = Qs[(ty + 16 * i) * 129 + kk];
            #pragma unroll
            for (int j = 0; j < 4; j++) kb[j] = Ks[(tx + 16 * j) * 129 + kk];
            #pragma unroll
            for (int i = 0; i < 4; i++)
                #pragma unroll
                for (int j = 0; j < 4; j++)
                    s[i][j] = fmaf(qa[i], kb[j], s[i][j]);
        }

        const bool diag = (kt == qt);
        #pragma unroll
        for (int i = 0; i < 4; i++) {
            const int qr = q0 + ty + 16 * i;
            #pragma unroll
            for (int j = 0; j < 4; j++) {
                const int kc = k0 + tx + 16 * j;
                float val = s[i][j];
                if (diag && kc > qr) val = -1e30f;
                Ps[(ty + 16 * i) * 65 + tx + 16 * j] = val;
            }
        }
        __syncthreads();

        if (tid < 64) {
            float* prow = Ps + tid * 65;
            float mOld = sm_m[tid];
            float mx = mOld;
            #pragma unroll 8
            for (int c = 0; c < 64; c++) mx = fmaxf(mx, prow[c]);
            const float alpha = __expf(mOld - mx);
            float sum = 0.f;
            #pragma unroll 8
            for (int c = 0; c < 64; c++) {
                const float p = __expf(prow[c] - mx);
                prow[c] = p;
                sum += p;
            }
            sm_l[tid] = sm_l[tid] * alpha + sum;
            sm_m[tid] = mx;
            sm_a[tid] = alpha;
        }
        __syncthreads();

        float al[4];
        #pragma unroll
        for (int i = 0; i < 4; i++) al[i] = sm_a[ty + 16 * i];
        #pragma unroll
        for (int i = 0; i < 4; i++)
            #pragma unroll
            for (int j = 0; j < 8; j++) acc[i][j] *= al[i];

        #pragma unroll 2
        for (int kk = 0; kk < BKT; kk++) {
            float p[4], vv[8];
            #pragma unroll
            for (int i = 0; i < 4; i++) p[i] = Ps[(ty + 16 * i) * 65 + kk];
            #pragma unroll
            for (int j = 0; j < 8; j++) vv[j] = Vs[kk * 129 + tx + 16 * j];
            #pragma unroll
            for (int i = 0; i < 4; i++)
                #pragma unroll
                for (int j = 0; j < 8; j++)
                    acc[i][j] = fmaf(p[i], vv[j], acc[i][j]);
        }
        __syncthreads();
    }

    #pragma unroll
    for (int i = 0; i < 4; i++) {
        const int r = ty + 16 * i;
        const float inv = 1.f / sm_l[r];
        const size_t base = (size_t)(b * S_ + q0 + r) * D_ + headoff;
        #pragma unroll
        for (int j = 0; j < 8; j++)
            o[base + tx + 16 * j] = acc[i][j] * inv;
    }
}

// ---------------- launch ---------------------------------------------------------
extern "C" void kernel_launch(void* const* d_in, const int* in_sizes, int n_in,
                              void* d_out, int out_size)
{
    const float* x  = (const float*)d_in[0];
    const float* Wq = (const float*)d_in[1];
    const float* bq = (const float*)d_in[2];
    const float* Wk = (const float*)d_in[3];
    const float* bk = (const float*)d_in[4];
    const float* Wv = (const float*)d_in[5];
    const float* bv = (const float*)d_in[6];
    const float* Wo = (const float*)d_in[7];
    const float* bo = (const float*)d_in[8];
    float* out = (float*)d_out;

    float *q, *k, *v, *ao;
    unsigned short *xhi, *xlo, *aohi, *aolo, *whi, *wlo;
    cudaGetSymbolAddress((void**)&q,    g_q);
    cudaGetSymbolAddress((void**)&k,    g_k);
    cudaGetSymbolAddress((void**)&v,    g_v);
    cudaGetSymbolAddress((void**)&ao,   g_ao);
    cudaGetSymbolAddress((void**)&xhi,  g_xhi);
    cudaGetSymbolAddress((void**)&xlo,  g_xlo);
    cudaGetSymbolAddress((void**)&aohi, g_aohi);
    cudaGetSymbolAddress((void**)&aolo, g_aolo);
    cudaGetSymbolAddress((void**)&whi,  g_whi);
    cudaGetSymbolAddress((void**)&wlo,  g_wlo);

    static bool attr_done = false;
    if (!attr_done) {
        cudaFuncSetAttribute(attn_kernel, cudaFuncAttributeMaxDynamicSharedMemorySize,
                             (int)(ATTN_SMEM_FLOATS * sizeof(float)));
        cudaFuncSetAttribute(gemm_mma_bf16x3, cudaFuncAttributeMaxDynamicSharedMemorySize,
                             GEMM_SMEM);
        attr_done = true;
    }

    const size_t wsz = (size_t)D_ * D_;
    const int nX4 = (M_ * D_) / 4;
    const int nW4 = (int)(wsz / 4);

    split_kernel<<<(nX4 + 255) / 256, 256>>>((const float4*)x, (ushort4*)xhi, (ushort4*)xlo, nX4);
    split_kernel<<<(nW4 + 255) / 256, 256>>>((const float4*)Wq, (ushort4*)(whi + 0 * wsz), (ushort4*)(wlo + 0 * wsz), nW4);
    split_kernel<<<(nW4 + 255) / 256, 256>>>((const float4*)Wk, (ushort4*)(whi + 1 * wsz), (ushort4*)(wlo + 1 * wsz), nW4);
    split_kernel<<<(nW4 + 255) / 256, 256>>>((const float4*)Wv, (ushort4*)(whi + 2 * wsz), (ushort4*)(wlo + 2 * wsz), nW4);
    split_kernel<<<(nW4 + 255) / 256, 256>>>((const float4*)Wo, (ushort4*)(whi + 3 * wsz), (ushort4*)(wlo + 3 * wsz), nW4);

    dim3 gGrid(D_ / 128, M_ / 128);   // (16, 32)
    const float qscale = 1.0f / sqrtf((float)HD_);

    gemm_mma_bf16x3<<<gGrid, 256, GEMM_SMEM>>>(xhi, xlo, whi + 0 * wsz, wlo + 0 * wsz, bq, q, qscale);
    gemm_mma_bf16x3<<<gGrid, 256, GEMM_SMEM>>>(xhi, xlo, whi + 1 * wsz, wlo + 1 * wsz, bk, k, 1.0f);
    gemm_mma_bf16x3<<<gGrid, 256, GEMM_SMEM>>>(xhi, xlo, whi + 2 * wsz, wlo + 2 * wsz, bv, v, 1.0f);

    dim3 aGrid(S_ / BQ, B_ * H_);     // (32, 32)
    attn_kernel<<<aGrid, 256, ATTN_SMEM_FLOATS * sizeof(float)>>>(q, k, v, ao);

    split_kernel<<<(nX4 + 255) / 256, 256>>>((const float4*)ao, (ushort4*)aohi, (ushort4*)aolo, nX4);
    gemm_mma_bf16x3<<<gGrid, 256, GEMM_SMEM>>>(aohi, aolo, whi + 3 * wsz, wlo + 3 * wsz, bo, out, 1.0f);
}

// round 5
// speedup vs baseline: 2.9715x; 1.6699x over previous
#include <cuda_runtime.h>
#include <cuda_bf16.h>
#include <math.h>
#include <stdint.h>

#define B_  2
#define S_  2048
#define H_  16
#define HD_ 128
#define D_  2048
#define M_  (B_ * S_)   // 4096

// ---------------- scratch (static device globals; no allocation) ----------------
__device__ unsigned short g_xhi[(size_t)M_ * D_];
__device__ unsigned short g_xlo[(size_t)M_ * D_];
__device__ unsigned short g_qhi[(size_t)M_ * D_];
__device__ unsigned short g_qlo[(size_t)M_ * D_];
__device__ unsigned short g_khi[(size_t)M_ * D_];
__device__ unsigned short g_klo[(size_t)M_ * D_];
__device__ unsigned short g_vhi[(size_t)M_ * D_];
__device__ unsigned short g_vlo[(size_t)M_ * D_];
__device__ unsigned short g_aohi[(size_t)M_ * D_];
__device__ unsigned short g_aolo[(size_t)M_ * D_];
__device__ unsigned short g_whi[4][(size_t)D_ * D_];
__device__ unsigned short g_wlo[4][(size_t)D_ * D_];

__device__ __forceinline__ uint32_t smem_to_u32(const void* p) {
    uint32_t a;
    asm("{ .reg .u64 t; cvta.to.shared.u64 t, %1; cvt.u32.u64 %0, t; }" : "=r"(a) : "l"(p));
    return a;
}

#define LDMATRIX_X4(r0, r1, r2, r3, addr) \
    asm volatile("ldmatrix.sync.aligned.m8n8.x4.shared.b16 {%0,%1,%2,%3}, [%4];" \
                 : "=r"(r0), "=r"(r1), "=r"(r2), "=r"(r3) : "r"(addr))
#define LDMATRIX_X4_T(r0, r1, r2, r3, addr) \
    asm volatile("ldmatrix.sync.aligned.m8n8.x4.trans.shared.b16 {%0,%1,%2,%3}, [%4];" \
                 : "=r"(r0), "=r"(r1), "=r"(r2), "=r"(r3) : "r"(addr))

#define MMA_BF16(d, a, b) \
    asm volatile("mma.sync.aligned.m16n8k16.row.col.f32.bf16.bf16.f32 " \
                 "{%0,%1,%2,%3}, {%4,%5,%6,%7}, {%8,%9}, {%0,%1,%2,%3};" \
                 : "+f"((d)[0]), "+f"((d)[1]), "+f"((d)[2]), "+f"((d)[3]) \
                 : "r"((a)[0]), "r"((a)[1]), "r"((a)[2]), "r"((a)[3]), \
                   "r"((b)[0]), "r"((b)[1]))

#define CP_ASYNC_16(dst, src) \
    asm volatile("cp.async.cg.shared.global [%0], [%1], 16;" :: "r"(dst), "l"(src))
#define CP_ASYNC_COMMIT() asm volatile("cp.async.commit_group;" ::: "memory")
#define CP_ASYNC_WAIT1()  asm volatile("cp.async.wait_group 1;" ::: "memory")

// pack two floats to bf16x2 (v0 -> low half), optionally returning residuals
__device__ __forceinline__ uint32_t pack2(float v0, float v1) {
    __nv_bfloat16 h0 = __float2bfloat16(v0), h1 = __float2bfloat16(v1);
    return (uint32_t)__bfloat16_as_ushort(h0) | ((uint32_t)__bfloat16_as_ushort(h1) << 16);
}
__device__ __forceinline__ uint32_t pack2r(float v0, float v1, float& r0, float& r1) {
    __nv_bfloat16 h0 = __float2bfloat16(v0), h1 = __float2bfloat16(v1);
    r0 = v0 - __bfloat162float(h0);
    r1 = v1 - __bfloat162float(h1);
    return (uint32_t)__bfloat16_as_ushort(h0) | ((uint32_t)__bfloat16_as_ushort(h1) << 16);
}

// ---------------- split fp32 -> bf16 hi/lo ---------------------------------------
__global__ __launch_bounds__(256) void split_kernel(
    const float4* __restrict__ in, ushort4* __restrict__ hi, ushort4* __restrict__ lo, int n4)
{
    int i = blockIdx.x * blockDim.x + threadIdx.x;
    if (i >= n4) return;
    float4 x = in[i];
    __nv_bfloat16 h0 = __float2bfloat16(x.x);
    __nv_bfloat16 h1 = __float2bfloat16(x.y);
    __nv_bfloat16 h2 = __float2bfloat16(x.z);
    __nv_bfloat16 h3 = __float2bfloat16(x.w);
    ushort4 hv, lv;
    hv.x = __bfloat16_as_ushort(h0);
    hv.y = __bfloat16_as_ushort(h1);
    hv.z = __bfloat16_as_ushort(h2);
    hv.w = __bfloat16_as_ushort(h3);
    lv.x = __bfloat16_as_ushort(__float2bfloat16(x.x - __bfloat162float(h0)));
    lv.y = __bfloat16_as_ushort(__float2bfloat16(x.y - __bfloat162float(h1)));
    lv.z = __bfloat16_as_ushort(__float2bfloat16(x.z - __bfloat162float(h2)));
    lv.w = __bfloat16_as_ushort(__float2bfloat16(x.w - __bfloat162float(h3)));
    hi[i] = hv;
    lo[i] = lv;
}

// ---------------- HMMA bf16x3 GEMM: C = scale*(A @ W^T + bias) -------------------
// Output either fp32 (Cf) or bf16 hi/lo (Chi/Clo) when Cf == nullptr.
#define BKC 32
#define NCH (D_ / BKC)             // 64
#define ROW_B 80                   // bytes per smem row (32 bf16 + 8 pad)
#define TILE_SB (128 * ROW_B)      // 10240 B per 128x32 tile
#define BUF_SB (4 * TILE_SB)       // Ahi, Alo, Bhi, Blo = 40960 B
#define GEMM_SMEM (2 * BUF_SB)     // 81920 B

__global__ __launch_bounds__(256) void gemm_mma_bf16x3(
    const unsigned short* __restrict__ Ahi, const unsigned short* __restrict__ Alo,
    const unsigned short* __restrict__ Bhi, const unsigned short* __restrict__ Blo,
    const float* __restrict__ bias, float* __restrict__ Cf,
    unsigned short* __restrict__ Chi, unsigned short* __restrict__ Clo, float scale)
{
    extern __shared__ __align__(16) unsigned short smem_us[];
    const uint32_t sb = smem_to_u32(smem_us);

    const int tid  = threadIdx.x;
    const int lane = tid & 31;
    const int wid  = tid >> 5;
    const int wm   = wid >> 2;
    const int wn   = wid & 3;
    const int bm   = blockIdx.y * 128;
    const int bn   = blockIdx.x * 128;

    float acc[4][4][4];
    #pragma unroll
    for (int i = 0; i < 4; i++)
        #pragma unroll
        for (int j = 0; j < 4; j++)
            #pragma unroll
            for (int r = 0; r < 4; r++) acc[i][j][r] = 0.f;

    auto load_chunk = [&](int c, int buf) {
        const int k0 = c * BKC;
        const uint32_t sbase = sb + buf * BUF_SB;
        #pragma unroll
        for (int t = 0; t < 8; t++) {
            const int tile = t >> 1;
            const int idx  = tid + (t & 1) * 256;
            const int r    = idx >> 2;
            const int c16  = idx & 3;
            const unsigned short* g =
                (tile == 0) ? Ahi : (tile == 1) ? Alo : (tile == 2) ? Bhi : Blo;
            const int grow = ((tile < 2) ? bm : bn) + r;
            const unsigned short* src = g + (size_t)grow * D_ + k0 + c16 * 8;
            const uint32_t dst = sbase + tile * TILE_SB + r * ROW_B + c16 * 16;
            CP_ASYNC_16(dst, src);
        }
        CP_ASYNC_COMMIT();
    };

    load_chunk(0, 0);
    load_chunk(1, 1);

    const int a_row  = wm * 64 + (lane & 15);
    const int a_cadd = (lane >> 4) * 8;
    const int b_i    = lane >> 3;
    const int b_row  = wn * 32 + (b_i >> 1) * 8 + (lane & 7);
    const int b_cadd = (b_i & 1) * 8;

    for (int c = 0; c < NCH; c++) {
        CP_ASYNC_WAIT1();
        __syncthreads();

        const uint32_t sbase = sb + (c & 1) * BUF_SB;
        const uint32_t ah_b = sbase;
        const uint32_t al_b = sbase + TILE_SB;
        const uint32_t bh_b = sbase + 2 * TILE_SB;
        const uint32_t bl_b = sbase + 3 * TILE_SB;

        #pragma unroll
        for (int ks = 0; ks < 2; ks++) {
            const int kb = ks * 16;
            uint32_t ah[4][4], al[4][4];
            #pragma unroll
            for (int mt = 0; mt < 4; mt++) {
                const uint32_t off = (uint32_t)(a_row + mt * 16) * ROW_B + (kb + a_cadd) * 2;
                LDMATRIX_X4(ah[mt][0], ah[mt][1], ah[mt][2], ah[mt][3], ah_b + off);
                LDMATRIX_X4(al[mt][0], al[mt][1], al[mt][2], al[mt][3], al_b + off);
            }
            uint32_t bh[4][2], bl[4][2];
            #pragma unroll
            for (int np = 0; np < 2; np++) {
                const uint32_t off = (uint32_t)(b_row + np * 16) * ROW_B + (kb + b_cadd) * 2;
                LDMATRIX_X4(bh[np*2][0], bh[np*2][1], bh[np*2+1][0], bh[np*2+1][1], bh_b + off);
                LDMATRIX_X4(bl[np*2][0], bl[np*2][1], bl[np*2+1][0], bl[np*2+1][1], bl_b + off);
            }
            #pragma unroll
            for (int mt = 0; mt < 4; mt++)
                #pragma unroll
                for (int nt = 0; nt < 4; nt++) {
                    MMA_BF16(acc[mt][nt], ah[mt], bh[nt]);
                    MMA_BF16(acc[mt][nt], ah[mt], bl[nt]);
                    MMA_BF16(acc[mt][nt], al[mt], bh[nt]);
                }
        }

        __syncthreads();
        if (c + 2 < NCH) load_chunk(c + 2, c & 1);
    }

    const int g  = lane >> 2;
    const int tq = lane & 3;
    #pragma unroll
    for (int nt = 0; nt < 4; nt++) {
        const int col = bn + wn * 32 + nt * 8 + tq * 2;
        const float b0 = bias[col], b1 = bias[col + 1];
        #pragma unroll
        for (int mt = 0; mt < 4; mt++) {
            const size_t r0 = (size_t)(bm + wm * 64 + mt * 16 + g);
            const float v00 = scale * (acc[mt][nt][0] + b0);
            const float v01 = scale * (acc[mt][nt][1] + b1);
            const float v10 = scale * (acc[mt][nt][2] + b0);
            const float v11 = scale * (acc[mt][nt][3] + b1);
            if (Cf) {
                *(float2*)(Cf + r0 * D_ + col)       = make_float2(v00, v01);
                *(float2*)(Cf + (r0 + 8) * D_ + col) = make_float2(v10, v11);
            } else {
                float ra, rb;
                const uint32_t h0 = pack2r(v00, v01, ra, rb);
                *(uint32_t*)(Chi + r0 * D_ + col) = h0;
                *(uint32_t*)(Clo + r0 * D_ + col) = pack2(ra, rb);
                const uint32_t h1 = pack2r(v10, v11, ra, rb);
                *(uint32_t*)(Chi + (r0 + 8) * D_ + col) = h1;
                *(uint32_t*)(Clo + (r0 + 8) * D_ + col) = pack2(ra, rb);
            }
        }
    }
}

// ---------------- HMMA flash attention (bf16x3, causal) --------------------------
// BQ=128 (8 warps x 16 rows), BK=64, hd=128. q prescaled by 1/sqrt(hd).
#define AROWB 272                       // 128 bf16 + 8 pad = 272 B (odd*16)
#define Q_SB  (128 * AROWB)             // 34816
#define KV_SB (64 * AROWB)              // 17408
#define KVBUF_SB (4 * KV_SB)            // 69632 (khi,klo,vhi,vlo)
#define ATTN_SMEM (2 * Q_SB + 2 * KVBUF_SB)   // 208896 B

__global__ __launch_bounds__(256) void attn_mma(
    const unsigned short* __restrict__ qhi, const unsigned short* __restrict__ qlo,
    const unsigned short* __restrict__ khi, const unsigned short* __restrict__ klo,
    const unsigned short* __restrict__ vhi, const unsigned short* __restrict__ vlo,
    unsigned short* __restrict__ aohi, unsigned short* __restrict__ aolo)
{
    extern __shared__ __align__(16) char asmem[];
    const uint32_t sb = smem_to_u32(asmem);
    const int tid = threadIdx.x, lane = tid & 31, wid = tid >> 5;
    const int g = lane >> 2, tq = lane & 3;
    const int qt = blockIdx.x, bh = blockIdx.y;
    const int b = bh >> 4, h = bh & 15;
    const int q0 = qt * 128;
    const int ktmax = 2 * qt + 1;
    const int headoff = h * HD_;

    // ---- Q tiles (hi/lo), one cp.async group ----
    #pragma unroll
    for (int t = 0; t < 16; t++) {
        const int tile = t >> 3;
        const int idx = (t & 7) * 256 + tid;     // 0..2047
        const int r = idx >> 4, seg = idx & 15;
        const unsigned short* src = (tile ? qlo : qhi)
            + (size_t)(b * S_ + q0 + r) * D_ + headoff + seg * 8;
        CP_ASYNC_16(sb + tile * Q_SB + r * AROWB + seg * 16, src);
    }
    CP_ASYNC_COMMIT();

    auto load_kv = [&](int kt, int buf) {
        const int k0 = kt * 64;
        const uint32_t kvb = sb + 2 * Q_SB + buf * KVBUF_SB;
        #pragma unroll
        for (int t = 0; t < 16; t++) {
            const int tile = t >> 2;             // 0 khi 1 klo 2 vhi 3 vlo
            const int idx = (t & 3) * 256 + tid; // 0..1023
            const int r = idx >> 4, seg = idx & 15;
            const unsigned short* base =
                (tile == 0) ? khi : (tile == 1) ? klo : (tile == 2) ? vhi : vlo;
            const unsigned short* src = base
                + (size_t)(b * S_ + k0 + r) * D_ + headoff + seg * 8;
            CP_ASYNC_16(kvb + tile * KV_SB + r * AROWB + seg * 16, src);
        }
        CP_ASYNC_COMMIT();
    };

    load_kv(0, 0);
    load_kv(1, 1);

    float o[16][4];
    #pragma unroll
    for (int j = 0; j < 16; j++)
        #pragma unroll
        for (int r = 0; r < 4; r++) o[j][r] = 0.f;
    float m0 = -INFINITY, m1 = -INFINITY, l0 = 0.f, l1 = 0.f;
    const int rowbase = q0 + wid * 16;

    // per-lane ldmatrix address parts
    const int arow   = wid * 16 + (lane & 15);
    const int acadd  = (lane >> 4) * 8;
    const int krow_p = (lane & 7) + ((lane >> 4) << 3);
    const int kc_p   = ((lane >> 3) & 1) * 8;
    const int vrow_p = lane & 15;
    const int vc_p   = (lane >> 4) * 8;

    for (int kt = 0; kt <= ktmax; kt++) {
        CP_ASYNC_WAIT1();
        __syncthreads();
        const int k0 = kt * 64;
        const uint32_t kvb = sb + 2 * Q_SB + (kt & 1) * KVBUF_SB;

        if (k0 <= rowbase + 15) {        // warp has at least one unmasked column
            float s[8][4];
            #pragma unroll
            for (int j = 0; j < 8; j++)
                #pragma unroll
                for (int r = 0; r < 4; r++) s[j][r] = 0.f;

            const uint32_t qh_b = sb, ql_b = sb + Q_SB;
            const uint32_t kh_b = kvb, kl_b = kvb + KV_SB;

            #pragma unroll
            for (int ks = 0; ks < 8; ks++) {
                uint32_t ah[4], al[4];
                const uint32_t aoff = (uint32_t)arow * AROWB + (ks * 16 + acadd) * 2;
                LDMATRIX_X4(ah[0], ah[1], ah[2], ah[3], qh_b + aoff);
                LDMATRIX_X4(al[0], al[1], al[2], al[3], ql_b + aoff);
                const uint32_t kcol = (uint32_t)(ks * 16 + kc_p) * 2;
                #pragma unroll
                for (int np = 0; np < 4; np++) {
                    uint32_t bhf[4], blf[4];
                    const uint32_t koff = (uint32_t)(16 * np + krow_p) * AROWB + kcol;
                    LDMATRIX_X4(bhf[0], bhf[1], bhf[2], bhf[3], kh_b + koff);
                    LDMATRIX_X4(blf[0], blf[1], blf[2], blf[3], kl_b + koff);
                    MMA_BF16(s[2*np],     ah, bhf);
                    MMA_BF16(s[2*np],     ah, blf);
                    MMA_BF16(s[2*np],     al, bhf);
                    MMA_BF16(s[2*np + 1], ah, bhf + 2);
                    MMA_BF16(s[2*np + 1], ah, blf + 2);
                    MMA_BF16(s[2*np + 1], al, bhf + 2);
                }
            }

            // causal mask (only near the diagonal)
            if (k0 + 63 > rowbase) {
                const int r0 = rowbase + g, r1 = r0 + 8;
                #pragma unroll
                for (int nt = 0; nt < 8; nt++) {
                    const int colb = k0 + nt * 8 + tq * 2;
                    if (colb     > r0) s[nt][0] = -1e30f;
                    if (colb + 1 > r0) s[nt][1] = -1e30f;
                    if (colb     > r1) s[nt][2] = -1e30f;
                    if (colb + 1 > r1) s[nt][3] = -1e30f;
                }
            }

            // online softmax (rows g and g+8, warp-local)
            float mx0 = -1e30f, mx1 = -1e30f;
            #pragma unroll
            for (int nt = 0; nt < 8; nt++) {
                mx0 = fmaxf(mx0, fmaxf(s[nt][0], s[nt][1]));
                mx1 = fmaxf(mx1, fmaxf(s[nt][2], s[nt][3]));
            }
            mx0 = fmaxf(mx0, __shfl_xor_sync(0xffffffffu, mx0, 1));
            mx0 = fmaxf(mx0, __shfl_xor_sync(0xffffffffu, mx0, 2));
            mx1 = fmaxf(mx1, __shfl_xor_sync(0xffffffffu, mx1, 1));
            mx1 = fmaxf(mx1, __shfl_xor_sync(0xffffffffu, mx1, 2));
            const float mn0 = fmaxf(m0, mx0), mn1 = fmaxf(m1, mx1);
            const float al0 = __expf(m0 - mn0), al1 = __expf(m1 - mn1);
            float sum0 = 0.f, sum1 = 0.f;
            #pragma unroll
            for (int nt = 0; nt < 8; nt++) {
                s[nt][0] = __expf(s[nt][0] - mn0);
                s[nt][1] = __expf(s[nt][1] - mn0);
                s[nt][2] = __expf(s[nt][2] - mn1);
                s[nt][3] = __expf(s[nt][3] - mn1);
                sum0 += s[nt][0] + s[nt][1];
                sum1 += s[nt][2] + s[nt][3];
            }
            sum0 += __shfl_xor_sync(0xffffffffu, sum0, 1);
            sum0 += __shfl_xor_sync(0xffffffffu, sum0, 2);
            sum1 += __shfl_xor_sync(0xffffffffu, sum1, 1);
            sum1 += __shfl_xor_sync(0xffffffffu, sum1, 2);
            l0 = l0 * al0 + sum0;  l1 = l1 * al1 + sum1;
            m0 = mn0;  m1 = mn1;
            #pragma unroll
            for (int j = 0; j < 16; j++) {
                o[j][0] *= al0; o[j][1] *= al0;
                o[j][2] *= al1; o[j][3] *= al1;
            }

            // PV: P (hi + residual lo) x V (hi/lo) via trans ldmatrix
            const uint32_t vh_b = kvb + 2 * KV_SB, vl_b = kvb + 3 * KV_SB;
            #pragma unroll
            for (int kk = 0; kk < 4; kk++) {
                uint32_t ph[4], pl[4];
                float ra, rb;
                ph[0] = pack2r(s[2*kk][0],     s[2*kk][1],     ra, rb); pl[0] = pack2(ra, rb);
                ph[1] = pack2r(s[2*kk][2],     s[2*kk][3],     ra, rb); pl[1] = pack2(ra, rb);
                ph[2] = pack2r(s[2*kk + 1][0], s[2*kk + 1][1], ra, rb); pl[2] = pack2(ra, rb);
                ph[3] = pack2r(s[2*kk + 1][2], s[2*kk + 1][3], ra, rb); pl[3] = pack2(ra, rb);
                const uint32_t vrow = (uint32_t)(kk * 16 + vrow_p) * AROWB;
                #pragma unroll
                for (int nb = 0; nb < 8; nb++) {
                    uint32_t vh[4], vl[4];
                    const uint32_t voff = vrow + (uint32_t)(nb * 16 + vc_p) * 2;
                    LDMATRIX_X4_T(vh[0], vh[1], vh[2], vh[3], vh_b + voff);
                    LDMATRIX_X4_T(vl[0], vl[1], vl[2], vl[3], vl_b + voff);
                    MMA_BF16(o[2*nb],     ph, vh);
                    MMA_BF16(o[2*nb],     ph, vl);
                    MMA_BF16(o[2*nb],     pl, vh);
                    MMA_BF16(o[2*nb + 1], ph, vh + 2);
                    MMA_BF16(o[2*nb + 1], ph, vl + 2);
                    MMA_BF16(o[2*nb + 1], pl, vh + 2);
                }
            }
        }

        __syncthreads();
        if (kt + 2 <= ktmax) load_kv(kt + 2, kt & 1);
    }

    // ---- epilogue: normalize, split hi/lo, store ----
    const float inv0 = 1.f / l0, inv1 = 1.f / l1;
    const size_t row0 = (size_t)(b * S_ + q0 + wid * 16 + g);
    #pragma unroll
    for (int nt = 0; nt < 16; nt++) {
        const int col = headoff + nt * 8 + tq * 2;
        const float v00 = o[nt][0] * inv0, v01 = o[nt][1] * inv0;
        const float v10 = o[nt][2] * inv1, v11 = o[nt][3] * inv1;
        float ra, rb;
        const uint32_t h0 = pack2r(v00, v01, ra, rb);
        *(uint32_t*)(aohi + row0 * D_ + col) = h0;
        *(uint32_t*)(aolo + row0 * D_ + col) = pack2(ra, rb);
        const uint32_t h1 = pack2r(v10, v11, ra, rb);
        *(uint32_t*)(aohi + (row0 + 8) * D_ + col) = h1;
        *(uint32_t*)(aolo + (row0 + 8) * D_ + col) = pack2(ra, rb);
    }
}

// ---------------- launch ---------------------------------------------------------
extern "C" void kernel_launch(void* const* d_in, const int* in_sizes, int n_in,
                              void* d_out, int out_size)
{
    const float* x  = (const float*)d_in[0];
    const float* Wq = (const float*)d_in[1];
    const float* bq = (const float*)d_in[2];
    const float* Wk = (const float*)d_in[3];
    const float* bk = (const float*)d_in[4];
    const float* Wv = (const float*)d_in[5];
    const float* bv = (const float*)d_in[6];
    const float* Wo = (const float*)d_in[7];
    const float* bo = (const float*)d_in[8];
    float* out = (float*)d_out;

    unsigned short *xhi, *xlo, *qhi, *qlo, *khi, *klo, *vhi, *vlo, *aohi, *aolo, *whi, *wlo;
    cudaGetSymbolAddress((void**)&xhi,  g_xhi);
    cudaGetSymbolAddress((void**)&xlo,  g_xlo);
    cudaGetSymbolAddress((void**)&qhi,  g_qhi);
    cudaGetSymbolAddress((void**)&qlo,  g_qlo);
    cudaGetSymbolAddress((void**)&khi,  g_khi);
    cudaGetSymbolAddress((void**)&klo,  g_klo);
    cudaGetSymbolAddress((void**)&vhi,  g_vhi);
    cudaGetSymbolAddress((void**)&vlo,  g_vlo);
    cudaGetSymbolAddress((void**)&aohi, g_aohi);
    cudaGetSymbolAddress((void**)&aolo, g_aolo);
    cudaGetSymbolAddress((void**)&whi,  g_whi);
    cudaGetSymbolAddress((void**)&wlo,  g_wlo);

    static bool attr_done = false;
    if (!attr_done) {
        cudaFuncSetAttribute(gemm_mma_bf16x3, cudaFuncAttributeMaxDynamicSharedMemorySize,
                             GEMM_SMEM);
        cudaFuncSetAttribute(attn_mma, cudaFuncAttributeMaxDynamicSharedMemorySize,
                             ATTN_SMEM);
        attr_done = true;
    }

    const size_t wsz = (size_t)D_ * D_;
    const int nX4 = (M_ * D_) / 4;
    const int nW4 = (int)(wsz / 4);

    split_kernel<<<(nX4 + 255) / 256, 256>>>((const float4*)x, (ushort4*)xhi, (ushort4*)xlo, nX4);
    split_kernel<<<(nW4 + 255) / 256, 256>>>((const float4*)Wq, (ushort4*)(whi + 0 * wsz), (ushort4*)(wlo + 0 * wsz), nW4);
    split_kernel<<<(nW4 + 255) / 256, 256>>>((const float4*)Wk, (ushort4*)(whi + 1 * wsz), (ushort4*)(wlo + 1 * wsz), nW4);
    split_kernel<<<(nW4 + 255) / 256, 256>>>((const float4*)Wv, (ushort4*)(whi + 2 * wsz), (ushort4*)(wlo + 2 * wsz), nW4);
    split_kernel<<<(nW4 + 255) / 256, 256>>>((const float4*)Wo, (ushort4*)(whi + 3 * wsz), (ushort4*)(wlo + 3 * wsz), nW4);

    dim3 gGrid(D_ / 128, M_ / 128);   // (16, 32)
    const float qscale = 1.0f / sqrtf((float)HD_);

    gemm_mma_bf16x3<<<gGrid, 256, GEMM_SMEM>>>(xhi, xlo, whi + 0 * wsz, wlo + 0 * wsz, bq,
                                               nullptr, qhi, qlo, qscale);
    gemm_mma_bf16x3<<<gGrid, 256, GEMM_SMEM>>>(xhi, xlo, whi + 1 * wsz, wlo + 1 * wsz, bk,
                                               nullptr, khi, klo, 1.0f);
    gemm_mma_bf16x3<<<gGrid, 256, GEMM_SMEM>>>(xhi, xlo, whi + 2 * wsz, wlo + 2 * wsz, bv,
                                               nullptr, vhi, vlo, 1.0f);

    dim3 aGrid(S_ / 128, B_ * H_);    // (16, 32)
    attn_mma<<<aGrid, 256, ATTN_SMEM>>>(qhi, qlo, khi, klo, vhi, vlo, aohi, aolo);

    gemm_mma_bf16x3<<<gGrid, 256, GEMM_SMEM>>>(aohi, aolo, whi + 3 * wsz, wlo + 3 * wsz, bo,
                                               out, nullptr, nullptr, 1.0f);
}

// round 7
// speedup vs baseline: 3.3242x; 1.1187x over previous
#include <cuda_runtime.h>
#include <cuda_bf16.h>
#include <math.h>
#include <stdint.h>

#define B_  2
#define S_  2048
#define H_  16
#define HD_ 128
#define D_  2048
#define M_  (B_ * S_)   // 4096

// ---------------- scratch (static device globals; no allocation) ----------------
__device__ unsigned short g_xhi[(size_t)M_ * D_];
__device__ unsigned short g_xlo[(size_t)M_ * D_];
__device__ unsigned short g_qhi[(size_t)M_ * D_];
__device__ unsigned short g_qlo[(size_t)M_ * D_];
__device__ unsigned short g_khi[(size_t)M_ * D_];
__device__ unsigned short g_klo[(size_t)M_ * D_];
__device__ unsigned short g_vhi[(size_t)M_ * D_];
__device__ unsigned short g_vlo[(size_t)M_ * D_];
__device__ unsigned short g_aohi[(size_t)M_ * D_];
__device__ unsigned short g_aolo[(size_t)M_ * D_];
__device__ unsigned short g_whi[4][(size_t)D_ * D_];
__device__ unsigned short g_wlo[4][(size_t)D_ * D_];

__device__ __forceinline__ uint32_t smem_to_u32(const void* p) {
    uint32_t a;
    asm("{ .reg .u64 t; cvta.to.shared.u64 t, %1; cvt.u32.u64 %0, t; }" : "=r"(a) : "l"(p));
    return a;
}

#define LDMATRIX_X4(r0, r1, r2, r3, addr) \
    asm volatile("ldmatrix.sync.aligned.m8n8.x4.shared.b16 {%0,%1,%2,%3}, [%4];" \
                 : "=r"(r0), "=r"(r1), "=r"(r2), "=r"(r3) : "r"(addr))
#define LDMATRIX_X4_T(r0, r1, r2, r3, addr) \
    asm volatile("ldmatrix.sync.aligned.m8n8.x4.trans.shared.b16 {%0,%1,%2,%3}, [%4];" \
                 : "=r"(r0), "=r"(r1), "=r"(r2), "=r"(r3) : "r"(addr))

#define MMA_BF16(d, a, b) \
    asm volatile("mma.sync.aligned.m16n8k16.row.col.f32.bf16.bf16.f32 " \
                 "{%0,%1,%2,%3}, {%4,%5,%6,%7}, {%8,%9}, {%0,%1,%2,%3};" \
                 : "+f"((d)[0]), "+f"((d)[1]), "+f"((d)[2]), "+f"((d)[3]) \
                 : "r"((a)[0]), "r"((a)[1]), "r"((a)[2]), "r"((a)[3]), \
                   "r"((b)[0]), "r"((b)[1]))

#define CP_ASYNC_16(dst, src) \
    asm volatile("cp.async.cg.shared.global [%0], [%1], 16;" :: "r"(dst), "l"(src))
#define CP_ASYNC_COMMIT() asm volatile("cp.async.commit_group;" ::: "memory")
#define CP_ASYNC_WAIT1()  asm volatile("cp.async.wait_group 1;" ::: "memory")

__device__ __forceinline__ uint32_t pack2(float v0, float v1) {
    __nv_bfloat16 h0 = __float2bfloat16(v0), h1 = __float2bfloat16(v1);
    return (uint32_t)__bfloat16_as_ushort(h0) | ((uint32_t)__bfloat16_as_ushort(h1) << 16);
}
__device__ __forceinline__ uint32_t pack2r(float v0, float v1, float& r0, float& r1) {
    __nv_bfloat16 h0 = __float2bfloat16(v0), h1 = __float2bfloat16(v1);
    r0 = v0 - __bfloat162float(h0);
    r1 = v1 - __bfloat162float(h1);
    return (uint32_t)__bfloat16_as_ushort(h0) | ((uint32_t)__bfloat16_as_ushort(h1) << 16);
}

// ---------------- split fp32 -> bf16 hi/lo ---------------------------------------
__global__ __launch_bounds__(256) void split_kernel(
    const float4* __restrict__ in, ushort4* __restrict__ hi, ushort4* __restrict__ lo, int n4)
{
    int i = blockIdx.x * blockDim.x + threadIdx.x;
    if (i >= n4) return;
    float4 x = in[i];
    __nv_bfloat16 h0 = __float2bfloat16(x.x);
    __nv_bfloat16 h1 = __float2bfloat16(x.y);
    __nv_bfloat16 h2 = __float2bfloat16(x.z);
    __nv_bfloat16 h3 = __float2bfloat16(x.w);
    ushort4 hv, lv;
    hv.x = __bfloat16_as_ushort(h0);
    hv.y = __bfloat16_as_ushort(h1);
    hv.z = __bfloat16_as_ushort(h2);
    hv.w = __bfloat16_as_ushort(h3);
    lv.x = __bfloat16_as_ushort(__float2bfloat16(x.x - __bfloat162float(h0)));
    lv.y = __bfloat16_as_ushort(__float2bfloat16(x.y - __bfloat162float(h1)));
    lv.z = __bfloat16_as_ushort(__float2bfloat16(x.z - __bfloat162float(h2)));
    lv.w = __bfloat16_as_ushort(__float2bfloat16(x.w - __bfloat162float(h3)));
    hi[i] = hv;
    lo[i] = lv;
}

// ---------------- HMMA bf16x3 GEMM: C = scale*(A @ W^T + bias) -------------------
// Block 256x128, 8 warps (warp tile 64x64), K-chunk 32, 3-stage cp.async pipeline.
#define BKC 32
#define NCH (D_ / BKC)             // 64
#define ROW_B 80                   // bytes per smem row (32 bf16 + 8 pad)
#define A_SB (256 * ROW_B)         // 20480 per A tensor tile (256x32)
#define Bt_SB (128 * ROW_B)        // 10240 per B tensor tile (128x32)
#define STAGE_SB (2 * A_SB + 2 * Bt_SB)   // 61440: Ahi, Alo, Bhi, Blo
#define GEMM_SMEM (3 * STAGE_SB)   // 184320
#define OFF_AHI 0
#define OFF_ALO A_SB
#define OFF_BHI (2 * A_SB)
#define OFF_BLO (2 * A_SB + Bt_SB)

__global__ __launch_bounds__(256, 1) void gemm_mma_bf16x3(
    const unsigned short* __restrict__ Ahi, const unsigned short* __restrict__ Alo,
    const unsigned short* __restrict__ Bhi, const unsigned short* __restrict__ Blo,
    const float* __restrict__ bias, float* __restrict__ Cf,
    unsigned short* __restrict__ Chi, unsigned short* __restrict__ Clo, float scale)
{
    extern __shared__ __align__(16) unsigned short smem_us[];
    const uint32_t sb = smem_to_u32(smem_us);

    const int tid  = threadIdx.x;
    const int lane = tid & 31;
    const int wid  = tid >> 5;       // 0..7
    const int wm   = wid >> 1;       // 0..3 -> rows wm*64
    const int wn   = wid & 1;        // 0..1 -> cols wn*64
    const int bm   = blockIdx.y * 256;
    const int bn   = blockIdx.x * 128;

    float acc[4][8][4];
    #pragma unroll
    for (int i = 0; i < 4; i++)
        #pragma unroll
        for (int j = 0; j < 8; j++)
            #pragma unroll
            for (int r = 0; r < 4; r++) acc[i][j][r] = 0.f;

    // 3072 16B segments per stage, 12 per thread
    auto load_chunk = [&](int c, int stg) {
        const int k0 = c * BKC;
        const uint32_t sbase = sb + stg * STAGE_SB;
        #pragma unroll
        for (int t = 0; t < 12; t++) {
            const int idx = t * 256 + tid;      // 0..3071
            const unsigned short* src;
            uint32_t dst;
            if (idx < 2048) {                   // A tiles: 1024 segs each
                const int which = idx >> 10;    // 0 hi, 1 lo
                const int ii = idx & 1023;
                const int r = ii >> 2, c16 = ii & 3;
                src = (which ? Alo : Ahi) + (size_t)(bm + r) * D_ + k0 + c16 * 8;
                dst = sbase + (which ? OFF_ALO : OFF_AHI) + r * ROW_B + c16 * 16;
            } else {                            // B tiles: 512 segs each
                const int ii = idx - 2048;
                const int which = ii >> 9;      // 0 hi, 1 lo
                const int jj = ii & 511;
                const int r = jj >> 2, c16 = jj & 3;
                src = (which ? Blo : Bhi) + (size_t)(bn + r) * D_ + k0 + c16 * 8;
                dst = sbase + (which ? OFF_BLO : OFF_BHI) + r * ROW_B + c16 * 16;
            }
            CP_ASYNC_16(dst, src);
        }
        CP_ASYNC_COMMIT();
    };

    load_chunk(0, 0);
    load_chunk(1, 1);

    // ldmatrix per-lane address parts
    const int a_row  = wm * 64 + (lane & 15);      // + mt*16
    const int a_cadd = (lane >> 4) * 8;            // + ks*16
    const int b_i    = lane >> 3;
    const int b_row  = wn * 64 + (b_i >> 1) * 8 + (lane & 7);   // + np*16
    const int b_cadd = (b_i & 1) * 8;              // + ks*16

    int stg = 0;
    for (int c = 0; c < NCH; c++) {
        CP_ASYNC_WAIT1();
        __syncthreads();

        if (c + 2 < NCH) {
            int nstg = stg + 2; if (nstg >= 3) nstg -= 3;
            load_chunk(c + 2, nstg);
        }

        const uint32_t sbase = sb + stg * STAGE_SB;
        const uint32_t ah_b = sbase + OFF_AHI;
        const uint32_t al_b = sbase + OFF_ALO;
        const uint32_t bh_b = sbase + OFF_BHI;
        const uint32_t bl_b = sbase + OFF_BLO;

        #pragma unroll
        for (int ks = 0; ks < 2; ks++) {
            const int kb = ks * 16;
            // B fragments: 8 n-tiles (hi+lo)
            uint32_t bh[8][2], bl[8][2];
            #pragma unroll
            for (int np = 0; np < 4; np++) {
                const uint32_t off = (uint32_t)(b_row + np * 16) * ROW_B + (kb + b_cadd) * 2;
                LDMATRIX_X4(bh[np*2][0], bh[np*2][1], bh[np*2+1][0], bh[np*2+1][1], bh_b + off);
                LDMATRIX_X4(bl[np*2][0], bl[np*2][1], bl[np*2+1][0], bl[np*2+1][1], bl_b + off);
            }
            #pragma unroll
            for (int mt = 0; mt < 4; mt++) {
                uint32_t ah[4], al[4];
                const uint32_t off = (uint32_t)(a_row + mt * 16) * ROW_B + (kb + a_cadd) * 2;
                LDMATRIX_X4(ah[0], ah[1], ah[2], ah[3], ah_b + off);
                LDMATRIX_X4(al[0], al[1], al[2], al[3], al_b + off);
                #pragma unroll
                for (int nt = 0; nt < 8; nt++) {
                    MMA_BF16(acc[mt][nt], ah, bh[nt]);
                    MMA_BF16(acc[mt][nt], ah, bl[nt]);
                    MMA_BF16(acc[mt][nt], al, bh[nt]);
                }
            }
        }

        if (++stg >= 3) stg -= 3;
    }

    // ---- epilogue ----
    const int g  = lane >> 2;
    const int tq = lane & 3;
    #pragma unroll
    for (int nt = 0; nt < 8; nt++) {
        const int col = bn + wn * 64 + nt * 8 + tq * 2;
        const float b0 = bias[col], b1 = bias[col + 1];
        #pragma unroll
        for (int mt = 0; mt < 4; mt++) {
            const size_t r0 = (size_t)(bm + wm * 64 + mt * 16 + g);
            const float v00 = scale * (acc[mt][nt][0] + b0);
            const float v01 = scale * (acc[mt][nt][1] + b1);
            const float v10 = scale * (acc[mt][nt][2] + b0);
            const float v11 = scale * (acc[mt][nt][3] + b1);
            if (Cf) {
                *(float2*)(Cf + r0 * D_ + col)       = make_float2(v00, v01);
                *(float2*)(Cf + (r0 + 8) * D_ + col) = make_float2(v10, v11);
            } else {
                float ra, rb;
                const uint32_t h0 = pack2r(v00, v01, ra, rb);
                *(uint32_t*)(Chi + r0 * D_ + col) = h0;
                *(uint32_t*)(Clo + r0 * D_ + col) = pack2(ra, rb);
                const uint32_t h1 = pack2r(v10, v11, ra, rb);
                *(uint32_t*)(Chi + (r0 + 8) * D_ + col) = h1;
                *(uint32_t*)(Clo + (r0 + 8) * D_ + col) = pack2(ra, rb);
            }
        }
    }
}

// ---------------- HMMA flash attention (bf16x3, causal) — unchanged from R5 ------
#define AROWB 272
#define Q_SB  (128 * AROWB)
#define KV_SB (64 * AROWB)
#define KVBUF_SB (4 * KV_SB)
#define ATTN_SMEM (2 * Q_SB + 2 * KVBUF_SB)

__global__ __launch_bounds__(256) void attn_mma(
    const unsigned short* __restrict__ qhi, const unsigned short* __restrict__ qlo,
    const unsigned short* __restrict__ khi, const unsigned short* __restrict__ klo,
    const unsigned short* __restrict__ vhi, const unsigned short* __restrict__ vlo,
    unsigned short* __restrict__ aohi, unsigned short* __restrict__ aolo)
{
    extern __shared__ __align__(16) char asmem[];
    const uint32_t sb = smem_to_u32(asmem);
    const int tid = threadIdx.x, lane = tid & 31, wid = tid >> 5;
    const int g = lane >> 2, tq = lane & 3;
    const int qt = blockIdx.x, bh = blockIdx.y;
    const int b = bh >> 4, h = bh & 15;
    const int q0 = qt * 128;
    const int ktmax = 2 * qt + 1;
    const int headoff = h * HD_;

    #pragma unroll
    for (int t = 0; t < 16; t++) {
        const int tile = t >> 3;
        const int idx = (t & 7) * 256 + tid;
        const int r = idx >> 4, seg = idx & 15;
        const unsigned short* src = (tile ? qlo : qhi)
            + (size_t)(b * S_ + q0 + r) * D_ + headoff + seg * 8;
        CP_ASYNC_16(sb + tile * Q_SB + r * AROWB + seg * 16, src);
    }
    CP_ASYNC_COMMIT();

    auto load_kv = [&](int kt, int buf) {
        const int k0 = kt * 64;
        const uint32_t kvb = sb + 2 * Q_SB + buf * KVBUF_SB;
        #pragma unroll
        for (int t = 0; t < 16; t++) {
            const int tile = t >> 2;
            const int idx = (t & 3) * 256 + tid;
            const int r = idx >> 4, seg = idx & 15;
            const unsigned short* base =
                (tile == 0) ? khi : (tile == 1) ? klo : (tile == 2) ? vhi : vlo;
            const unsigned short* src = base
                + (size_t)(b * S_ + k0 + r) * D_ + headoff + seg * 8;
            CP_ASYNC_16(kvb + tile * KV_SB + r * AROWB + seg * 16, src);
        }
        CP_ASYNC_COMMIT();
    };

    load_kv(0, 0);
    load_kv(1, 1);

    float o[16][4];
    #pragma unroll
    for (int j = 0; j < 16; j++)
        #pragma unroll
        for (int r = 0; r < 4; r++) o[j][r] = 0.f;
    float m0 = -INFINITY, m1 = -INFINITY, l0 = 0.f, l1 = 0.f;
    const int rowbase = q0 + wid * 16;

    const int arow   = wid * 16 + (lane & 15);
    const int acadd  = (lane >> 4) * 8;
    const int krow_p = (lane & 7) + ((lane >> 4) << 3);
    const int kc_p   = ((lane >> 3) & 1) * 8;
    const int vrow_p = lane & 15;
    const int vc_p   = (lane >> 4) * 8;

    for (int kt = 0; kt <= ktmax; kt++) {
        CP_ASYNC_WAIT1();
        __syncthreads();
        const int k0 = kt * 64;
        const uint32_t kvb = sb + 2 * Q_SB + (kt & 1) * KVBUF_SB;

        if (k0 <= rowbase + 15) {
            float s[8][4];
            #pragma unroll
            for (int j = 0; j < 8; j++)
                #pragma unroll
                for (int r = 0; r < 4; r++) s[j][r] = 0.f;

            const uint32_t qh_b = sb, ql_b = sb + Q_SB;
            const uint32_t kh_b = kvb, kl_b = kvb + KV_SB;

            #pragma unroll
            for (int ks = 0; ks < 8; ks++) {
                uint32_t ah[4], al[4];
                const uint32_t aoff = (uint32_t)arow * AROWB + (ks * 16 + acadd) * 2;
                LDMATRIX_X4(ah[0], ah[1], ah[2], ah[3], qh_b + aoff);
                LDMATRIX_X4(al[0], al[1], al[2], al[3], ql_b + aoff);
                const uint32_t kcol = (uint32_t)(ks * 16 + kc_p) * 2;
                #pragma unroll
                for (int np = 0; np < 4; np++) {
                    uint32_t bhf[4], blf[4];
                    const uint32_t koff = (uint32_t)(16 * np + krow_p) * AROWB + kcol;
                    LDMATRIX_X4(bhf[0], bhf[1], bhf[2], bhf[3], kh_b + koff);
                    LDMATRIX_X4(blf[0], blf[1], blf[2], blf[3], kl_b + koff);
                    MMA_BF16(s[2*np],     ah, bhf);
                    MMA_BF16(s[2*np],     ah, blf);
                    MMA_BF16(s[2*np],     al, bhf);
                    MMA_BF16(s[2*np + 1], ah, bhf + 2);
                    MMA_BF16(s[2*np + 1], ah, blf + 2);
                    MMA_BF16(s[2*np + 1], al, bhf + 2);
                }
            }

            if (k0 + 63 > rowbase) {
                const int r0 = rowbase + g, r1 = r0 + 8;
                #pragma unroll
                for (int nt = 0; nt < 8; nt++) {
                    const int colb = k0 + nt * 8 + tq * 2;
                    if (colb     > r0) s[nt][0] = -1e30f;
                    if (colb + 1 > r0) s[nt][1] = -1e30f;
                    if (colb     > r1) s[nt][2] = -1e30f;
                    if (colb + 1 > r1) s[nt][3] = -1e30f;
                }
            }

            float mx0 = -1e30f, mx1 = -1e30f;
            #pragma unroll
            for (int nt = 0; nt < 8; nt++) {
                mx0 = fmaxf(mx0, fmaxf(s[nt][0], s[nt][1]));
                mx1 = fmaxf(mx1, fmaxf(s[nt][2], s[nt][3]));
            }
            mx0 = fmaxf(mx0, __shfl_xor_sync(0xffffffffu, mx0, 1));
            mx0 = fmaxf(mx0, __shfl_xor_sync(0xffffffffu, mx0, 2));
            mx1 = fmaxf(mx1, __shfl_xor_sync(0xffffffffu, mx1, 1));
            mx1 = fmaxf(mx1, __shfl_xor_sync(0xffffffffu, mx1, 2));
            const float mn0 = fmaxf(m0, mx0), mn1 = fmaxf(m1, mx1);
            const float al0 = __expf(m0 - mn0), al1 = __expf(m1 - mn1);
            float sum0 = 0.f, sum1 = 0.f;
            #pragma unroll
            for (int nt = 0; nt < 8; nt++) {
                s[nt][0] = __expf(s[nt][0] - mn0);
                s[nt][1] = __expf(s[nt][1] - mn0);
                s[nt][2] = __expf(s[nt][2] - mn1);
                s[nt][3] = __expf(s[nt][3] - mn1);
                sum0 += s[nt][0] + s[nt][1];
                sum1 += s[nt][2] + s[nt][3];
            }
            sum0 += __shfl_xor_sync(0xffffffffu, sum0, 1);
            sum0 += __shfl_xor_sync(0xffffffffu, sum0, 2);
            sum1 += __shfl_xor_sync(0xffffffffu, sum1, 1);
            sum1 += __shfl_xor_sync(0xffffffffu, sum1, 2);
            l0 = l0 * al0 + sum0;  l1 = l1 * al1 + sum1;
            m0 = mn0;  m1 = mn1;
            #pragma unroll
            for (int j = 0; j < 16; j++) {
                o[j][0] *= al0; o[j][1] *= al0;
                o[j][2] *= al1; o[j][3] *= al1;
            }

            const uint32_t vh_b = kvb + 2 * KV_SB, vl_b = kvb + 3 * KV_SB;
            #pragma unroll
            for (int kk = 0; kk < 4; kk++) {
                uint32_t ph[4], pl[4];
                float ra, rb;
                ph[0] = pack2r(s[2*kk][0],     s[2*kk][1],     ra, rb); pl[0] = pack2(ra, rb);
                ph[1] = pack2r(s[2*kk][2],     s[2*kk][3],     ra, rb); pl[1] = pack2(ra, rb);
                ph[2] = pack2r(s[2*kk + 1][0], s[2*kk + 1][1], ra, rb); pl[2] = pack2(ra, rb);
                ph[3] = pack2r(s[2*kk + 1][2], s[2*kk + 1][3], ra, rb); pl[3] = pack2(ra, rb);
                const uint32_t vrow = (uint32_t)(kk * 16 + vrow_p) * AROWB;
                #pragma unroll
                for (int nb = 0; nb < 8; nb++) {
                    uint32_t vh[4], vl[4];
                    const uint32_t voff = vrow + (uint32_t)(nb * 16 + vc_p) * 2;
                    LDMATRIX_X4_T(vh[0], vh[1], vh[2], vh[3], vh_b + voff);
                    LDMATRIX_X4_T(vl[0], vl[1], vl[2], vl[3], vl_b + voff);
                    MMA_BF16(o[2*nb],     ph, vh);
                    MMA_BF16(o[2*nb],     ph, vl);
                    MMA_BF16(o[2*nb],     pl, vh);
                    MMA_BF16(o[2*nb + 1], ph, vh + 2);
                    MMA_BF16(o[2*nb + 1], ph, vl + 2);
                    MMA_BF16(o[2*nb + 1], pl, vh + 2);
                }
            }
        }

        __syncthreads();
        if (kt + 2 <= ktmax) load_kv(kt + 2, kt & 1);
    }

    const float inv0 = 1.f / l0, inv1 = 1.f / l1;
    const size_t row0 = (size_t)(b * S_ + q0 + wid * 16 + g);
    #pragma unroll
    for (int nt = 0; nt < 16; nt++) {
        const int col = headoff + nt * 8 + tq * 2;
        const float v00 = o[nt][0] * inv0, v01 = o[nt][1] * inv0;
        const float v10 = o[nt][2] * inv1, v11 = o[nt][3] * inv1;
        float ra, rb;
        const uint32_t h0 = pack2r(v00, v01, ra, rb);
        *(uint32_t*)(aohi + row0 * D_ + col) = h0;
        *(uint32_t*)(aolo + row0 * D_ + col) = pack2(ra, rb);
        const uint32_t h1 = pack2r(v10, v11, ra, rb);
        *(uint32_t*)(aohi + (row0 + 8) * D_ + col) = h1;
        *(uint32_t*)(aolo + (row0 + 8) * D_ + col) = pack2(ra, rb);
    }
}

// ---------------- launch ---------------------------------------------------------
extern "C" void kernel_launch(void* const* d_in, const int* in_sizes, int n_in,
                              void* d_out, int out_size)
{
    const float* x  = (const float*)d_in[0];
    const float* Wq = (const float*)d_in[1];
    const float* bq = (const float*)d_in[2];
    const float* Wk = (const float*)d_in[3];
    const float* bk = (const float*)d_in[4];
    const float* Wv = (const float*)d_in[5];
    const float* bv = (const float*)d_in[6];
    const float* Wo = (const float*)d_in[7];
    const float* bo = (const float*)d_in[8];
    float* out = (float*)d_out;

    unsigned short *xhi, *xlo, *qhi, *qlo, *khi, *klo, *vhi, *vlo, *aohi, *aolo, *whi, *wlo;
    cudaGetSymbolAddress((void**)&xhi,  g_xhi);
    cudaGetSymbolAddress((void**)&xlo,  g_xlo);
    cudaGetSymbolAddress((void**)&qhi,  g_qhi);
    cudaGetSymbolAddress((void**)&qlo,  g_qlo);
    cudaGetSymbolAddress((void**)&khi,  g_khi);
    cudaGetSymbolAddress((void**)&klo,  g_klo);
    cudaGetSymbolAddress((void**)&vhi,  g_vhi);
    cudaGetSymbolAddress((void**)&vlo,  g_vlo);
    cudaGetSymbolAddress((void**)&aohi, g_aohi);
    cudaGetSymbolAddress((void**)&aolo, g_aolo);
    cudaGetSymbolAddress((void**)&whi,  g_whi);
    cudaGetSymbolAddress((void**)&wlo,  g_wlo);

    static bool attr_done = false;
    if (!attr_done) {
        cudaFuncSetAttribute(gemm_mma_bf16x3, cudaFuncAttributeMaxDynamicSharedMemorySize,
                             GEMM_SMEM);
        cudaFuncSetAttribute(attn_mma, cudaFuncAttributeMaxDynamicSharedMemorySize,
                             ATTN_SMEM);
        attr_done = true;
    }

    const size_t wsz = (size_t)D_ * D_;
    const int nX4 = (M_ * D_) / 4;
    const int nW4 = (int)(wsz / 4);

    split_kernel<<<(nX4 + 255) / 256, 256>>>((const float4*)x, (ushort4*)xhi, (ushort4*)xlo, nX4);
    split_kernel<<<(nW4 + 255) / 256, 256>>>((const float4*)Wq, (ushort4*)(whi + 0 * wsz), (ushort4*)(wlo + 0 * wsz), nW4);
    split_kernel<<<(nW4 + 255) / 256, 256>>>((const float4*)Wk, (ushort4*)(whi + 1 * wsz), (ushort4*)(wlo + 1 * wsz), nW4);
    split_kernel<<<(nW4 + 255) / 256, 256>>>((const float4*)Wv, (ushort4*)(whi + 2 * wsz), (ushort4*)(wlo + 2 * wsz), nW4);
    split_kernel<<<(nW4 + 255) / 256, 256>>>((const float4*)Wo, (ushort4*)(whi + 3 * wsz), (ushort4*)(wlo + 3 * wsz), nW4);

    dim3 gGrid(D_ / 128, M_ / 256);   // (16, 16)
    const float qscale = 1.0f / sqrtf((float)HD_);

    gemm_mma_bf16x3<<<gGrid, 256, GEMM_SMEM>>>(xhi, xlo, whi + 0 * wsz, wlo + 0 * wsz, bq,
                                               nullptr, qhi, qlo, qscale);
    gemm_mma_bf16x3<<<gGrid, 256, GEMM_SMEM>>>(xhi, xlo, whi + 1 * wsz, wlo + 1 * wsz, bk,
                                               nullptr, khi, klo, 1.0f);
    gemm_mma_bf16x3<<<gGrid, 256, GEMM_SMEM>>>(xhi, xlo, whi + 2 * wsz, wlo + 2 * wsz, bv,
                                               nullptr, vhi, vlo, 1.0f);

    dim3 aGrid(S_ / 128, B_ * H_);    // (16, 32)
    attn_mma<<<aGrid, 256, ATTN_SMEM>>>(qhi, qlo, khi, klo, vhi, vlo, aohi, aolo);

    gemm_mma_bf16x3<<<gGrid, 256, GEMM_SMEM>>>(aohi, aolo, whi + 3 * wsz, wlo + 3 * wsz, bo,
                                               out, nullptr, nullptr, 1.0f);
}